// round 11
// baseline (speedup 1.0000x reference)
#include <cuda_runtime.h>
#include <cuda_bf16.h>
#include <stdint.h>
#include <math.h>

// Problem constants
#define BB 2
#define LL 2048
#define DM 768
#define DS 32
#define DC 7
#define DI 1536
#define BL (BB*LL)          // 4096
#define XPW (2*DS + DI)     // 1600
#define XZW (2*DI)          // 3072

#define NPAD2 1664          // Wx rows padded to multiple of 128

// SMEM geometry: K-chunk 32 bf16 = 64B data + 16B pad per row
#define ROWB 80
#define PLANE (128*ROWB)      // 10240 B
#define STAGE (4*PLANE)       // 40960 B (Ahi,Alo,Whi,Wlo)
#define SMEM_BYTES (2*STAGE)  // 81920 double-buffered -> 2 CTAs/SM

// ---------------- scratch (static device globals; no allocation) ----------------
__device__ float g_xz  [BL * XZW];     // xn @ Win^T  (xc_pre | z)
__device__ float g_bc  [BL * 64];      // compact B|C columns of xp
__device__ float4 g_pack[BL * DI];     // (delta, delta*xc, silu(z), xc*D*silu(z))

// bf16 split planes: A-side reused for xn -> xcv -> y ; W-side for Win -> Wx -> Wout
__device__ __align__(16) __nv_bfloat16 g_ahi[BL * DI];
__device__ __align__(16) __nv_bfloat16 g_alo[BL * DI];
__device__ __align__(16) __nv_bfloat16 g_whi[NPAD2 * DI];
__device__ __align__(16) __nv_bfloat16 g_wlo[NPAD2 * DI];

// ==================== PTX helpers (non-'a' features only) ====================
__device__ __forceinline__ uint32_t smem_u32(const void* p) {
    uint32_t a;
    asm("{ .reg .u64 t; cvta.to.shared.u64 t, %1; cvt.u32.u64 %0, t; }"
        : "=r"(a) : "l"(p));
    return a;
}
#define CP_ASYNC16(s, g) \
    asm volatile("cp.async.cg.shared.global [%0], [%1], 16;" :: "r"(s), "l"(g) : "memory")
#define CP_COMMIT() asm volatile("cp.async.commit_group;" ::: "memory")
#define CP_WAITG(n) asm volatile("cp.async.wait_group %0;" :: "n"(n) : "memory")

#define LDMX4(r0, r1, r2, r3, a) \
    asm volatile("ldmatrix.sync.aligned.m8n8.x4.shared.b16 {%0,%1,%2,%3}, [%4];" \
        : "=r"(r0), "=r"(r1), "=r"(r2), "=r"(r3) : "r"(a))

#define MMA_BF16(acc, aa, b0, b1) \
    asm volatile("mma.sync.aligned.m16n8k16.row.col.f32.bf16.bf16.f32 " \
        "{%0,%1,%2,%3}, {%4,%5,%6,%7}, {%8,%9}, {%0,%1,%2,%3};" \
        : "+f"((acc)[0]), "+f"((acc)[1]), "+f"((acc)[2]), "+f"((acc)[3]) \
        : "r"((aa)[0]), "r"((aa)[1]), "r"((aa)[2]), "r"((aa)[3]), \
          "r"(b0), "r"(b1))

// ---------------- fused scan-input pack (GEMM2 epilogue path) ----------------
__device__ __forceinline__ void pack_one(int row, int d, float val,
                                         const float* __restrict__ xz,
                                         const float* __restrict__ Dv)
{
    float delta = (val > 15.f) ? val : __logf(1.f + __expf(val));
    float xc = __bfloat162float(g_ahi[(size_t)row * DI + d])
             + __bfloat162float(g_alo[(size_t)row * DI + d]);
    float z  = xz[(size_t)row * XZW + DI + d];
    float gt = z / (1.f + __expf(-z));
    g_pack[(size_t)row * DI + d] = make_float4(delta, delta * xc, gt, xc * Dv[d] * gt);
}

// ==================== HMMA split-bf16 GEMM ====================
// C[m,n] = sum_k A[m,k]*W[n,k] (+Cadd). 128x128 CTA tile, 256 thr (8 warps 4Mx2N),
// K-chunk 32, double-buffered cp.async (wait_group 1 overlap), ldmatrix frags.
__device__ __forceinline__ void stage_copy(
    uint32_t sb, const __nv_bfloat16* gA, const __nv_bfloat16* gAl,
    const __nv_bfloat16* gW, const __nv_bfloat16* gWl, int Kst, int tid)
{
    #pragma unroll
    for (int h = 0; h < 2; h++) {
        int c = tid + h * 256;
        int row = c >> 2, part = c & 3;
        uint32_t so = (uint32_t)row * ROWB + part * 16;
        size_t go = (size_t)row * Kst + part * 8;
        CP_ASYNC16(sb + 0*PLANE + so, gA  + go);
        CP_ASYNC16(sb + 1*PLANE + so, gAl + go);
        CP_ASYNC16(sb + 2*PLANE + so, gW  + go);
        CP_ASYNC16(sb + 3*PLANE + so, gWl + go);
    }
}

template<int K, int NVALID, bool PACK>
__global__ void __launch_bounds__(256, 2) tc_gemm(
    const __nv_bfloat16* __restrict__ Ahi, const __nv_bfloat16* __restrict__ Alo,
    const __nv_bfloat16* __restrict__ Whi, const __nv_bfloat16* __restrict__ Wlo,
    const float* __restrict__ Cadd, float* __restrict__ Cout,
    const float* __restrict__ xz, const float* __restrict__ Dv)
{
    extern __shared__ char smem[];
    const int tid  = threadIdx.x;
    const int wid  = tid >> 5, lane = tid & 31;
    const int wm   = wid & 3;          // 0..3 -> 32-row slice
    const int wn   = wid >> 2;         // 0..1 -> 64-col slice
    const int row0 = blockIdx.y * 128, col0 = blockIdx.x * 128;
    const uint32_t sbase = smem_u32(smem);

    const __nv_bfloat16* pA  = Ahi + (size_t)row0 * K;
    const __nv_bfloat16* pAl = Alo + (size_t)row0 * K;
    const __nv_bfloat16* pW  = Whi + (size_t)col0 * K;
    const __nv_bfloat16* pWl = Wlo + (size_t)col0 * K;

    // ldmatrix lane addressing
    const int lr  = lane & 7;
    const int mlo = (lane >> 3) & 1;
    const int mhi = (lane >> 4) & 1;
    uint32_t aoff[2], boff[4];
    #pragma unroll
    for (int mt = 0; mt < 2; mt++)
        aoff[mt] = (uint32_t)(wm * 32 + mt * 16 + lr + mlo * 8) * ROWB + mhi * 16;
    #pragma unroll
    for (int np = 0; np < 4; np++)
        boff[np] = (uint32_t)(wn * 64 + np * 16 + lr + mhi * 8) * ROWB + mlo * 16;

    float acc[2][8][4];
    #pragma unroll
    for (int a = 0; a < 2; a++)
        #pragma unroll
        for (int b = 0; b < 8; b++)
            #pragma unroll
            for (int c = 0; c < 4; c++) acc[a][b][c] = 0.f;

    constexpr int NC = K / 32;

    stage_copy(sbase, pA, pAl, pW, pWl, K, tid);
    CP_COMMIT();

    #pragma unroll 1
    for (int c = 0; c < NC; ++c) {
        if (c + 1 < NC) {
            int ko = (c + 1) * 32;
            stage_copy(sbase + (uint32_t)((c + 1) & 1) * STAGE,
                       pA + ko, pAl + ko, pW + ko, pWl + ko, K, tid);
            CP_COMMIT();
            CP_WAITG(1);      // chunk c complete; chunk c+1 stays in flight
        } else {
            CP_WAITG(0);
        }
        __syncthreads();

        const uint32_t st = sbase + (uint32_t)(c & 1) * STAGE;
        #pragma unroll
        for (int ks = 0; ks < 2; ks++) {
            const uint32_t kb = ks * 32;   // 16 bf16 = 32 bytes
            uint32_t ah[2][4], al[2][4];
            #pragma unroll
            for (int mt = 0; mt < 2; mt++) {
                LDMX4(ah[mt][0], ah[mt][1], ah[mt][2], ah[mt][3],
                      st + 0*PLANE + aoff[mt] + kb);
                LDMX4(al[mt][0], al[mt][1], al[mt][2], al[mt][3],
                      st + 1*PLANE + aoff[mt] + kb);
            }
            #pragma unroll
            for (int np = 0; np < 4; np++) {
                uint32_t bh[4], bl[4];
                LDMX4(bh[0], bh[1], bh[2], bh[3], st + 2*PLANE + boff[np] + kb);
                LDMX4(bl[0], bl[1], bl[2], bl[3], st + 3*PLANE + boff[np] + kb);
                #pragma unroll
                for (int h = 0; h < 2; h++) {
                    const int nt = np * 2 + h;
                    #pragma unroll
                    for (int mt = 0; mt < 2; mt++) {
                        MMA_BF16(acc[mt][nt], ah[mt], bh[2*h], bh[2*h+1]);
                        MMA_BF16(acc[mt][nt], ah[mt], bl[2*h], bl[2*h+1]);
                        MMA_BF16(acc[mt][nt], al[mt], bh[2*h], bh[2*h+1]);
                    }
                }
            }
        }
        __syncthreads();
    }

    // Epilogue
    const int tg = lane & 3, gid = lane >> 2;
    #pragma unroll
    for (int mt = 0; mt < 2; mt++) {
        #pragma unroll
        for (int nt = 0; nt < 8; nt++) {
            int row = row0 + wm * 32 + mt * 16 + gid;
            int col = col0 + wn * 64 + nt * 8 + tg * 2;
            if (PACK) {
                if (col < 64) {
                    // compact B|C buffer
                    g_bc[(size_t)row * 64 + col]           = acc[mt][nt][0];
                    g_bc[(size_t)row * 64 + col + 1]       = acc[mt][nt][1];
                    g_bc[(size_t)(row + 8) * 64 + col]     = acc[mt][nt][2];
                    g_bc[(size_t)(row + 8) * 64 + col + 1] = acc[mt][nt][3];
                } else if (col < XPW) {
                    int d = col - 64;
                    pack_one(row,     d,     acc[mt][nt][0], xz, Dv);
                    pack_one(row,     d + 1, acc[mt][nt][1], xz, Dv);
                    pack_one(row + 8, d,     acc[mt][nt][2], xz, Dv);
                    pack_one(row + 8, d + 1, acc[mt][nt][3], xz, Dv);
                }
            } else {
                if (col < NVALID) {
                    size_t o0 = (size_t)row * NVALID + col;
                    size_t o1 = (size_t)(row + 8) * NVALID + col;
                    float2 v0 = make_float2(acc[mt][nt][0], acc[mt][nt][1]);
                    float2 v1 = make_float2(acc[mt][nt][2], acc[mt][nt][3]);
                    if (Cadd) {
                        float2 c0 = *(const float2*)(Cadd + o0);
                        float2 c1 = *(const float2*)(Cadd + o1);
                        v0.x += c0.x; v0.y += c0.y;
                        v1.x += c1.x; v1.y += c1.y;
                    }
                    *(float2*)(Cout + o0) = v0;
                    *(float2*)(Cout + o1) = v1;
                }
            }
        }
    }
}

// ==================== fp32 -> bf16 hi/lo split (weights only) ====================
__device__ __forceinline__ uint32_t pk2(__nv_bfloat16 a, __nv_bfloat16 b) {
    unsigned short ua = *(unsigned short*)&a, ub = *(unsigned short*)&b;
    return (uint32_t)ua | ((uint32_t)ub << 16);
}
__global__ __launch_bounds__(256) void cvt_split(
    const float4* __restrict__ src, uint2* __restrict__ hi, uint2* __restrict__ lo,
    int n4, int nvalid4)
{
    int i = blockIdx.x * 256 + threadIdx.x;
    if (i >= n4) return;
    float4 v = (i < nvalid4) ? src[i] : make_float4(0.f, 0.f, 0.f, 0.f);
    __nv_bfloat16 h0 = __float2bfloat16(v.x), h1 = __float2bfloat16(v.y);
    __nv_bfloat16 h2 = __float2bfloat16(v.z), h3 = __float2bfloat16(v.w);
    __nv_bfloat16 l0 = __float2bfloat16(v.x - __bfloat162float(h0));
    __nv_bfloat16 l1 = __float2bfloat16(v.y - __bfloat162float(h1));
    __nv_bfloat16 l2 = __float2bfloat16(v.z - __bfloat162float(h2));
    __nv_bfloat16 l3 = __float2bfloat16(v.w - __bfloat162float(h3));
    uint2 H, L;
    H.x = pk2(h0, h1); H.y = pk2(h2, h3);
    L.x = pk2(l0, l1); L.y = pk2(l2, l3);
    hi[i] = H; lo[i] = L;
}

// ---------------- LayerNorm -> bf16 hi/lo planes ----------------
__global__ __launch_bounds__(256) void ln_kernel(
    const float* __restrict__ x, const float* __restrict__ g,
    const float* __restrict__ b)
{
    int row = blockIdx.x;
    const float* xr = x + (size_t)row * DM;
    float s = 0.f, s2 = 0.f;
    for (int i = threadIdx.x; i < DM; i += 256) {
        float v = xr[i];
        s += v; s2 += v * v;
    }
    #pragma unroll
    for (int o = 16; o; o >>= 1) {
        s  += __shfl_xor_sync(0xffffffffu, s,  o);
        s2 += __shfl_xor_sync(0xffffffffu, s2, o);
    }
    __shared__ float red[16];
    __shared__ float mu_s, rs_s;
    int wid = threadIdx.x >> 5, lane = threadIdx.x & 31;
    if (lane == 0) { red[wid] = s; red[8 + wid] = s2; }
    __syncthreads();
    if (threadIdx.x == 0) {
        float S = 0.f, S2 = 0.f;
        #pragma unroll
        for (int i = 0; i < 8; i++) { S += red[i]; S2 += red[8 + i]; }
        float mu = S / (float)DM;
        float var = S2 / (float)DM - mu * mu;
        mu_s = mu;
        rs_s = rsqrtf(var + 1e-5f);
    }
    __syncthreads();
    float mu = mu_s, rs = rs_s;
    for (int i = threadIdx.x; i < DM; i += 256) {
        float v = (xr[i] - mu) * rs * g[i] + b[i];
        __nv_bfloat16 h = __float2bfloat16(v);
        g_ahi[(size_t)row * DM + i] = h;
        g_alo[(size_t)row * DM + i] = __float2bfloat16(v - __bfloat162float(h));
    }
}

// ---------------- depthwise causal conv (DC=7) + SiLU -> bf16 hi/lo ----------------
__global__ __launch_bounds__(256) void conv_silu_kernel(
    const float* __restrict__ cw, const float* __restrict__ cb)
{
    int idx = blockIdx.x * 256 + threadIdx.x;
    int d   = idx % DI;
    int row = idx / DI;
    int t   = row & (LL - 1);
    float s = cb[d];
    #pragma unroll
    for (int k = 0; k < DC; k++) {
        int tt = t - (DC - 1) + k;
        if (tt >= 0)
            s = fmaf(g_xz[(size_t)(row - (DC - 1) + k) * XZW + d], cw[d * DC + k], s);
    }
    float r = s / (1.f + __expf(-s));
    __nv_bfloat16 h = __float2bfloat16(r);
    g_ahi[idx] = h;
    g_alo[idx] = __float2bfloat16(r - __bfloat162float(h));
}

// ---------------- selective scan: 1 warp = 2 channels (d, d+DI/2), lane = state ----
__global__ __launch_bounds__(128) void scan_kernel(const float* __restrict__ A_log)
{
    int w    = blockIdx.x * 4 + (threadIdx.x >> 5);   // 0 .. BB*DI/2-1
    int lane = threadIdx.x & 31;
    int b  = w / (DI / 2);
    int dd = w - b * (DI / 2);
    int d0 = dd, d1 = dd + DI / 2;

    const float LOG2E = 1.4426950408889634f;
    float An0 = -__expf(A_log[d0 * DS + lane]) * LOG2E;
    float An1 = -__expf(A_log[d1 * DS + lane]) * LOG2E;

    const float*  pB  = g_bc   + (size_t)b * LL * 64 + lane;
    const float4* pk0 = g_pack + (size_t)b * LL * DI + d0;
    const float4* pk1 = g_pack + (size_t)b * LL * DI + d1;
    __nv_bfloat16* ph0 = g_ahi + (size_t)b * LL * DI + d0;
    __nv_bfloat16* pl0 = g_alo + (size_t)b * LL * DI + d0;
    __nv_bfloat16* ph1 = g_ahi + (size_t)b * LL * DI + d1;
    __nv_bfloat16* pl1 = g_alo + (size_t)b * LL * DI + d1;

    float h0 = 0.f, h1 = 0.f;
    #pragma unroll 4
    for (int t = 0; t < LL; ++t) {
        float Bn = pB[0];
        float Cn = pB[32];
        float4 P0 = *pk0;
        float4 P1 = *pk1;
        h0 = fmaf(exp2f(P0.x * An0), h0, P0.y * Bn);
        h1 = fmaf(exp2f(P1.x * An1), h1, P1.y * Bn);
        float p0 = h0 * Cn;
        float p1 = h1 * Cn;
        #pragma unroll
        for (int o = 16; o; o >>= 1) {
            p0 += __shfl_xor_sync(0xffffffffu, p0, o);
            p1 += __shfl_xor_sync(0xffffffffu, p1, o);
        }
        if (lane == 0) {
            float y0 = fmaf(p0, P0.z, P0.w);
            float y1 = fmaf(p1, P1.z, P1.w);
            __nv_bfloat16 yh0 = __float2bfloat16(y0);
            __nv_bfloat16 yh1 = __float2bfloat16(y1);
            ph0[0] = yh0;
            pl0[0] = __float2bfloat16(y0 - __bfloat162float(yh0));
            ph1[0] = yh1;
            pl1[0] = __float2bfloat16(y1 - __bfloat162float(yh1));
        }
        pB += 64; pk0 += DI; pk1 += DI;
        ph0 += DI; pl0 += DI; ph1 += DI; pl1 += DI;
    }
}

// ---------------- launch ----------------
extern "C" void kernel_launch(void* const* d_in, const int* in_sizes, int n_in,
                              void* d_out, int out_size)
{
    (void)in_sizes; (void)n_in; (void)out_size;
    const float* x      = (const float*)d_in[0];
    const float* Win    = (const float*)d_in[1];
    const float* conv_w = (const float*)d_in[2];
    const float* conv_b = (const float*)d_in[3];
    const float* Wx     = (const float*)d_in[4];
    const float* A_log  = (const float*)d_in[5];
    const float* Dv     = (const float*)d_in[6];
    const float* Wout   = (const float*)d_in[7];
    const float* ln_g   = (const float*)d_in[8];
    const float* ln_b   = (const float*)d_in[9];
    float* out = (float*)d_out;

    void *p_xz, *p_ahi, *p_alo, *p_whi, *p_wlo;
    cudaGetSymbolAddress(&p_xz,  g_xz);
    cudaGetSymbolAddress(&p_ahi, g_ahi);
    cudaGetSymbolAddress(&p_alo, g_alo);
    cudaGetSymbolAddress(&p_whi, g_whi);
    cudaGetSymbolAddress(&p_wlo, g_wlo);

    const __nv_bfloat16* ahi = (const __nv_bfloat16*)p_ahi;
    const __nv_bfloat16* alo = (const __nv_bfloat16*)p_alo;
    const __nv_bfloat16* whi = (const __nv_bfloat16*)p_whi;
    const __nv_bfloat16* wlo = (const __nv_bfloat16*)p_wlo;

    cudaFuncSetAttribute((const void*)tc_gemm<768, XZW, false>,
                         cudaFuncAttributeMaxDynamicSharedMemorySize, SMEM_BYTES);
    cudaFuncSetAttribute((const void*)tc_gemm<1536, XPW, true>,
                         cudaFuncAttributeMaxDynamicSharedMemorySize, SMEM_BYTES);
    cudaFuncSetAttribute((const void*)tc_gemm<1536, DM, false>,
                         cudaFuncAttributeMaxDynamicSharedMemorySize, SMEM_BYTES);

    // 1. LayerNorm (writes xn hi/lo planes directly)
    ln_kernel<<<BL, 256>>>(x, ln_g, ln_b);

    // 2. split-convert Win (3072x768)
    cvt_split<<<2304, 256>>>((const float4*)Win, (uint2*)p_whi, (uint2*)p_wlo,
                             589824, 589824);

    // 3. xz = xn @ Win^T   (4096 x 3072 x 768)
    tc_gemm<768, XZW, false><<<dim3(24, 32), 256, SMEM_BYTES>>>(
        ahi, alo, whi, wlo, nullptr, (float*)p_xz, nullptr, nullptr);

    // 4. depthwise conv + silu (writes xcv hi/lo planes directly)
    conv_silu_kernel<<<(BL * DI) / 256, 256>>>(conv_w, conv_b);

    // 5. split-convert Wx (1600x1536 -> padded 1664)
    cvt_split<<<2496, 256>>>((const float4*)Wx, (uint2*)p_whi, (uint2*)p_wlo,
                             638976, 614400);

    // 6. xp GEMM with fused pack epilogue: writes g_bc + g_pack directly
    tc_gemm<1536, XPW, true><<<dim3(13, 32), 256, SMEM_BYTES>>>(
        ahi, alo, whi, wlo, nullptr, nullptr, (const float*)p_xz, Dv);

    // 7. selective scan (2 channels per warp; writes y hi/lo planes directly)
    scan_kernel<<<(BB * DI / 2) / 4, 128>>>(A_log);

    // 8. split-convert Wout (768x1536)
    cvt_split<<<1152, 256>>>((const float4*)Wout, (uint2*)p_whi, (uint2*)p_wlo,
                             294912, 294912);

    // 9. out = y @ Wout^T + x   (4096 x 768 x 1536)
    tc_gemm<1536, DM, false><<<dim3(6, 32), 256, SMEM_BYTES>>>(
        ahi, alo, whi, wlo, x, out, nullptr, nullptr);
}

// round 13
// speedup vs baseline: 1.0862x; 1.0862x over previous
#include <cuda_runtime.h>
#include <cuda_bf16.h>
#include <stdint.h>
#include <math.h>

// Problem constants
#define BB 2
#define LL 2048
#define DM 768
#define DS 32
#define DC 7
#define DI 1536
#define BL (BB*LL)          // 4096
#define XPW (2*DS + DI)     // 1600
#define XZW (2*DI)          // 3072

#define NPAD2 1664          // Wx rows padded to multiple of 128

// SMEM geometry: K-chunk 32 bf16 = 64B data + 16B pad per row
#define ROWB 80
#define PLANE (128*ROWB)      // 10240 B
#define STAGE (4*PLANE)       // 40960 B (Ahi,Alo,Whi,Wlo)
#define SMEM_BYTES (2*STAGE)  // 81920 double-buffered -> 2 CTAs/SM

// ---------------- scratch (static device globals; no allocation) ----------------
__device__ float g_xz  [BL * XZW];     // xn @ Win^T  (xc_pre | z)
__device__ float g_xp  [BL * XPW];     // xcv @ Wx^T  (B | C | delta_raw)
__device__ float4 g_pack[BL * DI];     // (delta, delta*xc, silu(z), xc*D*silu(z))

// bf16 split planes: A-side reused for xn -> xcv -> y ; per-GEMM W planes
__device__ __align__(16) __nv_bfloat16 g_ahi [BL * DI];
__device__ __align__(16) __nv_bfloat16 g_alo [BL * DI];
__device__ __align__(16) __nv_bfloat16 g_whi1[XZW * DM];
__device__ __align__(16) __nv_bfloat16 g_wlo1[XZW * DM];
__device__ __align__(16) __nv_bfloat16 g_whi2[NPAD2 * DI];
__device__ __align__(16) __nv_bfloat16 g_wlo2[NPAD2 * DI];
__device__ __align__(16) __nv_bfloat16 g_whi3[DM * DI];
__device__ __align__(16) __nv_bfloat16 g_wlo3[DM * DI];

// ==================== PTX helpers (non-'a' features only) ====================
__device__ __forceinline__ uint32_t smem_u32(const void* p) {
    uint32_t a;
    asm("{ .reg .u64 t; cvta.to.shared.u64 t, %1; cvt.u32.u64 %0, t; }"
        : "=r"(a) : "l"(p));
    return a;
}
#define CP_ASYNC16(s, g) \
    asm volatile("cp.async.cg.shared.global [%0], [%1], 16;" :: "r"(s), "l"(g) : "memory")
#define CP_COMMIT() asm volatile("cp.async.commit_group;" ::: "memory")
#define CP_WAITG(n) asm volatile("cp.async.wait_group %0;" :: "n"(n) : "memory")

#define LDMX4(r0, r1, r2, r3, a) \
    asm volatile("ldmatrix.sync.aligned.m8n8.x4.shared.b16 {%0,%1,%2,%3}, [%4];" \
        : "=r"(r0), "=r"(r1), "=r"(r2), "=r"(r3) : "r"(a))

#define MMA_BF16(acc, aa, b0, b1) \
    asm volatile("mma.sync.aligned.m16n8k16.row.col.f32.bf16.bf16.f32 " \
        "{%0,%1,%2,%3}, {%4,%5,%6,%7}, {%8,%9}, {%0,%1,%2,%3};" \
        : "+f"((acc)[0]), "+f"((acc)[1]), "+f"((acc)[2]), "+f"((acc)[3]) \
        : "r"((aa)[0]), "r"((aa)[1]), "r"((aa)[2]), "r"((aa)[3]), \
          "r"(b0), "r"(b1))

// ==================== HMMA split-bf16 GEMM (R8 config) ====================
__device__ __forceinline__ void stage_copy(
    uint32_t sb, const __nv_bfloat16* gA, const __nv_bfloat16* gAl,
    const __nv_bfloat16* gW, const __nv_bfloat16* gWl, int Kst, int tid)
{
    #pragma unroll
    for (int h = 0; h < 2; h++) {
        int c = tid + h * 256;
        int row = c >> 2, part = c & 3;
        uint32_t so = (uint32_t)row * ROWB + part * 16;
        size_t go = (size_t)row * Kst + part * 8;
        CP_ASYNC16(sb + 0*PLANE + so, gA  + go);
        CP_ASYNC16(sb + 1*PLANE + so, gAl + go);
        CP_ASYNC16(sb + 2*PLANE + so, gW  + go);
        CP_ASYNC16(sb + 3*PLANE + so, gWl + go);
    }
}

template<int K, int NVALID>
__global__ void __launch_bounds__(256, 2) tc_gemm(
    const __nv_bfloat16* __restrict__ Ahi, const __nv_bfloat16* __restrict__ Alo,
    const __nv_bfloat16* __restrict__ Whi, const __nv_bfloat16* __restrict__ Wlo,
    const float* __restrict__ Cadd, float* __restrict__ Cout)
{
    extern __shared__ char smem[];
    const int tid  = threadIdx.x;
    const int wid  = tid >> 5, lane = tid & 31;
    const int wm   = wid & 3;
    const int wn   = wid >> 2;
    const int row0 = blockIdx.y * 128, col0 = blockIdx.x * 128;
    const uint32_t sbase = smem_u32(smem);

    const __nv_bfloat16* pA  = Ahi + (size_t)row0 * K;
    const __nv_bfloat16* pAl = Alo + (size_t)row0 * K;
    const __nv_bfloat16* pW  = Whi + (size_t)col0 * K;
    const __nv_bfloat16* pWl = Wlo + (size_t)col0 * K;

    const int lr  = lane & 7;
    const int mlo = (lane >> 3) & 1;
    const int mhi = (lane >> 4) & 1;
    uint32_t aoff[2], boff[4];
    #pragma unroll
    for (int mt = 0; mt < 2; mt++)
        aoff[mt] = (uint32_t)(wm * 32 + mt * 16 + lr + mlo * 8) * ROWB + mhi * 16;
    #pragma unroll
    for (int np = 0; np < 4; np++)
        boff[np] = (uint32_t)(wn * 64 + np * 16 + lr + mhi * 8) * ROWB + mlo * 16;

    float acc[2][8][4];
    #pragma unroll
    for (int a = 0; a < 2; a++)
        #pragma unroll
        for (int b = 0; b < 8; b++)
            #pragma unroll
            for (int c = 0; c < 4; c++) acc[a][b][c] = 0.f;

    constexpr int NC = K / 32;

    stage_copy(sbase, pA, pAl, pW, pWl, K, tid);
    CP_COMMIT();

    #pragma unroll 1
    for (int c = 0; c < NC; ++c) {
        if (c + 1 < NC) {
            int ko = (c + 1) * 32;
            stage_copy(sbase + (uint32_t)((c + 1) & 1) * STAGE,
                       pA + ko, pAl + ko, pW + ko, pWl + ko, K, tid);
            CP_COMMIT();
            CP_WAITG(1);
        } else {
            CP_WAITG(0);
        }
        __syncthreads();

        const uint32_t st = sbase + (uint32_t)(c & 1) * STAGE;
        #pragma unroll
        for (int ks = 0; ks < 2; ks++) {
            const uint32_t kb = ks * 32;
            uint32_t ah[2][4], al[2][4];
            #pragma unroll
            for (int mt = 0; mt < 2; mt++) {
                LDMX4(ah[mt][0], ah[mt][1], ah[mt][2], ah[mt][3],
                      st + 0*PLANE + aoff[mt] + kb);
                LDMX4(al[mt][0], al[mt][1], al[mt][2], al[mt][3],
                      st + 1*PLANE + aoff[mt] + kb);
            }
            #pragma unroll
            for (int np = 0; np < 4; np++) {
                uint32_t bh[4], bl[4];
                LDMX4(bh[0], bh[1], bh[2], bh[3], st + 2*PLANE + boff[np] + kb);
                LDMX4(bl[0], bl[1], bl[2], bl[3], st + 3*PLANE + boff[np] + kb);
                #pragma unroll
                for (int h = 0; h < 2; h++) {
                    const int nt = np * 2 + h;
                    #pragma unroll
                    for (int mt = 0; mt < 2; mt++) {
                        MMA_BF16(acc[mt][nt], ah[mt], bh[2*h], bh[2*h+1]);
                        MMA_BF16(acc[mt][nt], ah[mt], bl[2*h], bl[2*h+1]);
                        MMA_BF16(acc[mt][nt], al[mt], bh[2*h], bh[2*h+1]);
                    }
                }
            }
        }
        __syncthreads();
    }

    const int tg = lane & 3, gid = lane >> 2;
    #pragma unroll
    for (int mt = 0; mt < 2; mt++) {
        #pragma unroll
        for (int nt = 0; nt < 8; nt++) {
            int row = row0 + wm * 32 + mt * 16 + gid;
            int col = col0 + wn * 64 + nt * 8 + tg * 2;
            if (col < NVALID) {
                size_t o0 = (size_t)row * NVALID + col;
                size_t o1 = (size_t)(row + 8) * NVALID + col;
                float2 v0 = make_float2(acc[mt][nt][0], acc[mt][nt][1]);
                float2 v1 = make_float2(acc[mt][nt][2], acc[mt][nt][3]);
                if (Cadd) {
                    float2 c0 = *(const float2*)(Cadd + o0);
                    float2 c1 = *(const float2*)(Cadd + o1);
                    v0.x += c0.x; v0.y += c0.y;
                    v1.x += c1.x; v1.y += c1.y;
                }
                *(float2*)(Cout + o0) = v0;
                *(float2*)(Cout + o1) = v1;
            }
        }
    }
}

// ==================== fp32 -> bf16 hi/lo split (weights only) ====================
__device__ __forceinline__ uint32_t pk2(__nv_bfloat16 a, __nv_bfloat16 b) {
    unsigned short ua = *(unsigned short*)&a, ub = *(unsigned short*)&b;
    return (uint32_t)ua | ((uint32_t)ub << 16);
}
__global__ __launch_bounds__(256) void cvt_split(
    const float4* __restrict__ src, uint2* __restrict__ hi, uint2* __restrict__ lo,
    int n4, int nvalid4)
{
    int i = blockIdx.x * 256 + threadIdx.x;
    if (i >= n4) return;
    float4 v = (i < nvalid4) ? src[i] : make_float4(0.f, 0.f, 0.f, 0.f);
    __nv_bfloat16 h0 = __float2bfloat16(v.x), h1 = __float2bfloat16(v.y);
    __nv_bfloat16 h2 = __float2bfloat16(v.z), h3 = __float2bfloat16(v.w);
    __nv_bfloat16 l0 = __float2bfloat16(v.x - __bfloat162float(h0));
    __nv_bfloat16 l1 = __float2bfloat16(v.y - __bfloat162float(h1));
    __nv_bfloat16 l2 = __float2bfloat16(v.z - __bfloat162float(h2));
    __nv_bfloat16 l3 = __float2bfloat16(v.w - __bfloat162float(h3));
    uint2 H, L;
    H.x = pk2(h0, h1); H.y = pk2(h2, h3);
    L.x = pk2(l0, l1); L.y = pk2(l2, l3);
    hi[i] = H; lo[i] = L;
}

// ---------------- LayerNorm -> bf16 hi/lo planes ----------------
__global__ __launch_bounds__(256) void ln_kernel(
    const float* __restrict__ x, const float* __restrict__ g,
    const float* __restrict__ b)
{
    int row = blockIdx.x;
    const float* xr = x + (size_t)row * DM;
    float s = 0.f, s2 = 0.f;
    for (int i = threadIdx.x; i < DM; i += 256) {
        float v = xr[i];
        s += v; s2 += v * v;
    }
    #pragma unroll
    for (int o = 16; o; o >>= 1) {
        s  += __shfl_xor_sync(0xffffffffu, s,  o);
        s2 += __shfl_xor_sync(0xffffffffu, s2, o);
    }
    __shared__ float red[16];
    __shared__ float mu_s, rs_s;
    int wid = threadIdx.x >> 5, lane = threadIdx.x & 31;
    if (lane == 0) { red[wid] = s; red[8 + wid] = s2; }
    __syncthreads();
    if (threadIdx.x == 0) {
        float S = 0.f, S2 = 0.f;
        #pragma unroll
        for (int i = 0; i < 8; i++) { S += red[i]; S2 += red[8 + i]; }
        float mu = S / (float)DM;
        float var = S2 / (float)DM - mu * mu;
        mu_s = mu;
        rs_s = rsqrtf(var + 1e-5f);
    }
    __syncthreads();
    float mu = mu_s, rs = rs_s;
    for (int i = threadIdx.x; i < DM; i += 256) {
        float v = (xr[i] - mu) * rs * g[i] + b[i];
        __nv_bfloat16 h = __float2bfloat16(v);
        g_ahi[(size_t)row * DM + i] = h;
        g_alo[(size_t)row * DM + i] = __float2bfloat16(v - __bfloat162float(h));
    }
}

// ---------------- depthwise causal conv (DC=7) + SiLU -> bf16 hi/lo ----------------
__global__ __launch_bounds__(256) void conv_silu_kernel(
    const float* __restrict__ cw, const float* __restrict__ cb)
{
    int idx = blockIdx.x * 256 + threadIdx.x;
    int d   = idx % DI;
    int row = idx / DI;
    int t   = row & (LL - 1);
    float s = cb[d];
    #pragma unroll
    for (int k = 0; k < DC; k++) {
        int tt = t - (DC - 1) + k;
        if (tt >= 0)
            s = fmaf(g_xz[(size_t)(row - (DC - 1) + k) * XZW + d], cw[d * DC + k], s);
    }
    float r = s / (1.f + __expf(-s));
    __nv_bfloat16 h = __float2bfloat16(r);
    g_ahi[idx] = h;
    g_alo[idx] = __float2bfloat16(r - __bfloat162float(h));
}

// ---------------- precompute packed scan inputs ----------------
__global__ __launch_bounds__(256) void pre_kernel(const float* __restrict__ Dv)
{
    int idx = blockIdx.x * 256 + threadIdx.x;
    int d   = idx % DI;
    int row = idx / DI;
    float xv = g_xp[(size_t)row * XPW + 2 * DS + d];
    float delta = (xv > 15.f) ? xv : __logf(1.f + __expf(xv));
    float xc = __bfloat162float(g_ahi[idx]) + __bfloat162float(g_alo[idx]);
    float z  = g_xz[(size_t)row * XZW + DI + d];
    float gt = z / (1.f + __expf(-z));
    g_pack[idx] = make_float4(delta, delta * xc, gt, xc * Dv[d] * gt);
}

// ---------------- selective scan: 1 warp per (b,d), lane = state n ----------------
__global__ __launch_bounds__(128) void scan_kernel(const float* __restrict__ A_log)
{
    int wid  = blockIdx.x * 4 + (threadIdx.x >> 5);
    int lane = threadIdx.x & 31;
    int b = wid / DI;
    int d = wid - b * DI;

    float An2 = -__expf(A_log[d * DS + lane]) * 1.4426950408889634f;

    const float*  pB = g_xp   + (size_t)b * LL * XPW + lane;
    const float4* pk = g_pack + (size_t)b * LL * DI + d;
    __nv_bfloat16* pyh = g_ahi + (size_t)b * LL * DI + d;
    __nv_bfloat16* pyl = g_alo + (size_t)b * LL * DI + d;

    float h = 0.f;
    #pragma unroll 4
    for (int t = 0; t < LL; ++t) {
        float Bn = pB[0];
        float Cn = pB[DS];
        float4 P = *pk;
        float dA = exp2f(P.x * An2);
        h = fmaf(dA, h, P.y * Bn);
        float p = h * Cn;
        p += __shfl_xor_sync(0xffffffffu, p, 16);
        p += __shfl_xor_sync(0xffffffffu, p, 8);
        p += __shfl_xor_sync(0xffffffffu, p, 4);
        p += __shfl_xor_sync(0xffffffffu, p, 2);
        p += __shfl_xor_sync(0xffffffffu, p, 1);
        if (lane == 0) {
            float yv = fmaf(p, P.z, P.w);
            __nv_bfloat16 yh = __float2bfloat16(yv);
            pyh[0] = yh;
            pyl[0] = __float2bfloat16(yv - __bfloat162float(yh));
        }
        pB += XPW; pk += DI; pyh += DI; pyl += DI;
    }
}

// ---------------- launch ----------------
extern "C" void kernel_launch(void* const* d_in, const int* in_sizes, int n_in,
                              void* d_out, int out_size)
{
    (void)in_sizes; (void)n_in; (void)out_size;
    const float* x      = (const float*)d_in[0];
    const float* Win    = (const float*)d_in[1];
    const float* conv_w = (const float*)d_in[2];
    const float* conv_b = (const float*)d_in[3];
    const float* Wx     = (const float*)d_in[4];
    const float* A_log  = (const float*)d_in[5];
    const float* Dv     = (const float*)d_in[6];
    const float* Wout   = (const float*)d_in[7];
    const float* ln_g   = (const float*)d_in[8];
    const float* ln_b   = (const float*)d_in[9];
    float* out = (float*)d_out;

    void *p_xz, *p_xp, *p_ahi, *p_alo;
    void *p_whi1, *p_wlo1, *p_whi2, *p_wlo2, *p_whi3, *p_wlo3;
    cudaGetSymbolAddress(&p_xz,  g_xz);
    cudaGetSymbolAddress(&p_xp,  g_xp);
    cudaGetSymbolAddress(&p_ahi, g_ahi);
    cudaGetSymbolAddress(&p_alo, g_alo);
    cudaGetSymbolAddress(&p_whi1, g_whi1);
    cudaGetSymbolAddress(&p_wlo1, g_wlo1);
    cudaGetSymbolAddress(&p_whi2, g_whi2);
    cudaGetSymbolAddress(&p_wlo2, g_wlo2);
    cudaGetSymbolAddress(&p_whi3, g_whi3);
    cudaGetSymbolAddress(&p_wlo3, g_wlo3);

    const __nv_bfloat16* ahi = (const __nv_bfloat16*)p_ahi;
    const __nv_bfloat16* alo = (const __nv_bfloat16*)p_alo;

    cudaFuncSetAttribute((const void*)tc_gemm<768, XZW>,
                         cudaFuncAttributeMaxDynamicSharedMemorySize, SMEM_BYTES);
    cudaFuncSetAttribute((const void*)tc_gemm<1536, XPW>,
                         cudaFuncAttributeMaxDynamicSharedMemorySize, SMEM_BYTES);
    cudaFuncSetAttribute((const void*)tc_gemm<1536, DM>,
                         cudaFuncAttributeMaxDynamicSharedMemorySize, SMEM_BYTES);

    // 0. split-convert Win (3072x768)
    cvt_split<<<2304, 256>>>((const float4*)Win, (uint2*)p_whi1, (uint2*)p_wlo1,
                             589824, 589824);

    // 1. split-convert Wx (1600x1536 -> padded 1664)
    cvt_split<<<2496, 256>>>((const float4*)Wx, (uint2*)p_whi2, (uint2*)p_wlo2,
                             638976, 614400);

    // 2. LayerNorm (writes xn hi/lo planes directly)
    ln_kernel<<<BL, 256>>>(x, ln_g, ln_b);

    // 3. xz = xn @ Win^T   (4096 x 3072 x 768)   [profiled launch index 3]
    tc_gemm<768, XZW><<<dim3(24, 32), 256, SMEM_BYTES>>>(
        ahi, alo, (const __nv_bfloat16*)p_whi1, (const __nv_bfloat16*)p_wlo1,
        nullptr, (float*)p_xz);

    // 4. depthwise conv + silu (writes xcv hi/lo planes directly)
    conv_silu_kernel<<<(BL * DI) / 256, 256>>>(conv_w, conv_b);

    // 5. xp = xcv @ Wx^T   (4096 x 1600 x 1536)
    tc_gemm<1536, XPW><<<dim3(13, 32), 256, SMEM_BYTES>>>(
        ahi, alo, (const __nv_bfloat16*)p_whi2, (const __nv_bfloat16*)p_wlo2,
        nullptr, (float*)p_xp);

    // 6. precompute packed scan inputs
    pre_kernel<<<(BL * DI) / 256, 256>>>(Dv);

    // 7. selective scan (writes y hi/lo planes directly)
    scan_kernel<<<(BB * DI) / 4, 128>>>(A_log);

    // 8. split-convert Wout (768x1536)
    cvt_split<<<1152, 256>>>((const float4*)Wout, (uint2*)p_whi3, (uint2*)p_wlo3,
                             294912, 294912);

    // 9. out = y @ Wout^T + x   (4096 x 768 x 1536)
    tc_gemm<1536, DM><<<dim3(6, 32), 256, SMEM_BYTES>>>(
        ahi, alo, (const __nv_bfloat16*)p_whi3, (const __nv_bfloat16*)p_wlo3,
        x, out);
}

// round 14
// speedup vs baseline: 1.6703x; 1.5377x over previous
#include <cuda_runtime.h>
#include <cuda_bf16.h>
#include <stdint.h>
#include <math.h>

// Problem constants
#define BB 2
#define LL 2048
#define DM 768
#define DS 32
#define DC 7
#define DI 1536
#define BL (BB*LL)          // 4096
#define XPW (2*DS + DI)     // 1600
#define XZW (2*DI)          // 3072

#define NPAD2 1664          // Wx rows padded to multiple of 128
#define NSEG 8
#define SEGLEN (LL/NSEG)    // 256

// SMEM geometry: K-chunk 32 bf16 = 64B data + 16B pad per row
#define ROWB 80
#define PLANE (128*ROWB)      // 10240 B
#define STAGE (4*PLANE)       // 40960 B (Ahi,Alo,Whi,Wlo)
#define SMEM_BYTES (2*STAGE)  // 81920 double-buffered -> 2 CTAs/SM

// ---------------- scratch (static device globals; no allocation) ----------------
__device__ float g_xz  [BL * XZW];     // xn @ Win^T  (xc_pre | z)
__device__ float g_xp  [BL * XPW];     // xcv @ Wx^T  (B | C | delta_raw)
__device__ float4 g_pack[BL * DI];     // (delta, delta*xc, silu(z), xc*D*silu(z))
__device__ float2 g_seg [BB * DI * NSEG * DS];  // per-segment (h_end, aprod)
__device__ float  g_init[BB * DI * NSEG * DS];  // per-segment h_init

// bf16 split planes: A-side reused for xn -> xcv -> y ; per-GEMM W planes
__device__ __align__(16) __nv_bfloat16 g_ahi [BL * DI];
__device__ __align__(16) __nv_bfloat16 g_alo [BL * DI];
__device__ __align__(16) __nv_bfloat16 g_whi1[XZW * DM];
__device__ __align__(16) __nv_bfloat16 g_wlo1[XZW * DM];
__device__ __align__(16) __nv_bfloat16 g_whi2[NPAD2 * DI];
__device__ __align__(16) __nv_bfloat16 g_wlo2[NPAD2 * DI];
__device__ __align__(16) __nv_bfloat16 g_whi3[DM * DI];
__device__ __align__(16) __nv_bfloat16 g_wlo3[DM * DI];

// ==================== PTX helpers (non-'a' features only) ====================
__device__ __forceinline__ uint32_t smem_u32(const void* p) {
    uint32_t a;
    asm("{ .reg .u64 t; cvta.to.shared.u64 t, %1; cvt.u32.u64 %0, t; }"
        : "=r"(a) : "l"(p));
    return a;
}
#define CP_ASYNC16(s, g) \
    asm volatile("cp.async.cg.shared.global [%0], [%1], 16;" :: "r"(s), "l"(g) : "memory")
#define CP_COMMIT() asm volatile("cp.async.commit_group;" ::: "memory")
#define CP_WAITG(n) asm volatile("cp.async.wait_group %0;" :: "n"(n) : "memory")

#define LDMX4(r0, r1, r2, r3, a) \
    asm volatile("ldmatrix.sync.aligned.m8n8.x4.shared.b16 {%0,%1,%2,%3}, [%4];" \
        : "=r"(r0), "=r"(r1), "=r"(r2), "=r"(r3) : "r"(a))

#define MMA_BF16(acc, aa, b0, b1) \
    asm volatile("mma.sync.aligned.m16n8k16.row.col.f32.bf16.bf16.f32 " \
        "{%0,%1,%2,%3}, {%4,%5,%6,%7}, {%8,%9}, {%0,%1,%2,%3};" \
        : "+f"((acc)[0]), "+f"((acc)[1]), "+f"((acc)[2]), "+f"((acc)[3]) \
        : "r"((aa)[0]), "r"((aa)[1]), "r"((aa)[2]), "r"((aa)[3]), \
          "r"(b0), "r"(b1))

// ==================== HMMA split-bf16 GEMM (R8 config) ====================
__device__ __forceinline__ void stage_copy(
    uint32_t sb, const __nv_bfloat16* gA, const __nv_bfloat16* gAl,
    const __nv_bfloat16* gW, const __nv_bfloat16* gWl, int Kst, int tid)
{
    #pragma unroll
    for (int h = 0; h < 2; h++) {
        int c = tid + h * 256;
        int row = c >> 2, part = c & 3;
        uint32_t so = (uint32_t)row * ROWB + part * 16;
        size_t go = (size_t)row * Kst + part * 8;
        CP_ASYNC16(sb + 0*PLANE + so, gA  + go);
        CP_ASYNC16(sb + 1*PLANE + so, gAl + go);
        CP_ASYNC16(sb + 2*PLANE + so, gW  + go);
        CP_ASYNC16(sb + 3*PLANE + so, gWl + go);
    }
}

template<int K, int NVALID>
__global__ void __launch_bounds__(256, 2) tc_gemm(
    const __nv_bfloat16* __restrict__ Ahi, const __nv_bfloat16* __restrict__ Alo,
    const __nv_bfloat16* __restrict__ Whi, const __nv_bfloat16* __restrict__ Wlo,
    const float* __restrict__ Cadd, float* __restrict__ Cout)
{
    extern __shared__ char smem[];
    const int tid  = threadIdx.x;
    const int wid  = tid >> 5, lane = tid & 31;
    const int wm   = wid & 3;
    const int wn   = wid >> 2;
    const int row0 = blockIdx.y * 128, col0 = blockIdx.x * 128;
    const uint32_t sbase = smem_u32(smem);

    const __nv_bfloat16* pA  = Ahi + (size_t)row0 * K;
    const __nv_bfloat16* pAl = Alo + (size_t)row0 * K;
    const __nv_bfloat16* pW  = Whi + (size_t)col0 * K;
    const __nv_bfloat16* pWl = Wlo + (size_t)col0 * K;

    const int lr  = lane & 7;
    const int mlo = (lane >> 3) & 1;
    const int mhi = (lane >> 4) & 1;
    uint32_t aoff[2], boff[4];
    #pragma unroll
    for (int mt = 0; mt < 2; mt++)
        aoff[mt] = (uint32_t)(wm * 32 + mt * 16 + lr + mlo * 8) * ROWB + mhi * 16;
    #pragma unroll
    for (int np = 0; np < 4; np++)
        boff[np] = (uint32_t)(wn * 64 + np * 16 + lr + mhi * 8) * ROWB + mlo * 16;

    float acc[2][8][4];
    #pragma unroll
    for (int a = 0; a < 2; a++)
        #pragma unroll
        for (int b = 0; b < 8; b++)
            #pragma unroll
            for (int c = 0; c < 4; c++) acc[a][b][c] = 0.f;

    constexpr int NC = K / 32;

    stage_copy(sbase, pA, pAl, pW, pWl, K, tid);
    CP_COMMIT();

    #pragma unroll 1
    for (int c = 0; c < NC; ++c) {
        if (c + 1 < NC) {
            int ko = (c + 1) * 32;
            stage_copy(sbase + (uint32_t)((c + 1) & 1) * STAGE,
                       pA + ko, pAl + ko, pW + ko, pWl + ko, K, tid);
            CP_COMMIT();
            CP_WAITG(1);
        } else {
            CP_WAITG(0);
        }
        __syncthreads();

        const uint32_t st = sbase + (uint32_t)(c & 1) * STAGE;
        #pragma unroll
        for (int ks = 0; ks < 2; ks++) {
            const uint32_t kb = ks * 32;
            uint32_t ah[2][4], al[2][4];
            #pragma unroll
            for (int mt = 0; mt < 2; mt++) {
                LDMX4(ah[mt][0], ah[mt][1], ah[mt][2], ah[mt][3],
                      st + 0*PLANE + aoff[mt] + kb);
                LDMX4(al[mt][0], al[mt][1], al[mt][2], al[mt][3],
                      st + 1*PLANE + aoff[mt] + kb);
            }
            #pragma unroll
            for (int np = 0; np < 4; np++) {
                uint32_t bh[4], bl[4];
                LDMX4(bh[0], bh[1], bh[2], bh[3], st + 2*PLANE + boff[np] + kb);
                LDMX4(bl[0], bl[1], bl[2], bl[3], st + 3*PLANE + boff[np] + kb);
                #pragma unroll
                for (int h = 0; h < 2; h++) {
                    const int nt = np * 2 + h;
                    #pragma unroll
                    for (int mt = 0; mt < 2; mt++) {
                        MMA_BF16(acc[mt][nt], ah[mt], bh[2*h], bh[2*h+1]);
                        MMA_BF16(acc[mt][nt], ah[mt], bl[2*h], bl[2*h+1]);
                        MMA_BF16(acc[mt][nt], al[mt], bh[2*h], bh[2*h+1]);
                    }
                }
            }
        }
        __syncthreads();
    }

    const int tg = lane & 3, gid = lane >> 2;
    #pragma unroll
    for (int mt = 0; mt < 2; mt++) {
        #pragma unroll
        for (int nt = 0; nt < 8; nt++) {
            int row = row0 + wm * 32 + mt * 16 + gid;
            int col = col0 + wn * 64 + nt * 8 + tg * 2;
            if (col < NVALID) {
                size_t o0 = (size_t)row * NVALID + col;
                size_t o1 = (size_t)(row + 8) * NVALID + col;
                float2 v0 = make_float2(acc[mt][nt][0], acc[mt][nt][1]);
                float2 v1 = make_float2(acc[mt][nt][2], acc[mt][nt][3]);
                if (Cadd) {
                    float2 c0 = *(const float2*)(Cadd + o0);
                    float2 c1 = *(const float2*)(Cadd + o1);
                    v0.x += c0.x; v0.y += c0.y;
                    v1.x += c1.x; v1.y += c1.y;
                }
                *(float2*)(Cout + o0) = v0;
                *(float2*)(Cout + o1) = v1;
            }
        }
    }
}

// ==================== fp32 -> bf16 hi/lo split (weights only) ====================
__device__ __forceinline__ uint32_t pk2(__nv_bfloat16 a, __nv_bfloat16 b) {
    unsigned short ua = *(unsigned short*)&a, ub = *(unsigned short*)&b;
    return (uint32_t)ua | ((uint32_t)ub << 16);
}
__global__ __launch_bounds__(256) void cvt_split(
    const float4* __restrict__ src, uint2* __restrict__ hi, uint2* __restrict__ lo,
    int n4, int nvalid4)
{
    int i = blockIdx.x * 256 + threadIdx.x;
    if (i >= n4) return;
    float4 v = (i < nvalid4) ? src[i] : make_float4(0.f, 0.f, 0.f, 0.f);
    __nv_bfloat16 h0 = __float2bfloat16(v.x), h1 = __float2bfloat16(v.y);
    __nv_bfloat16 h2 = __float2bfloat16(v.z), h3 = __float2bfloat16(v.w);
    __nv_bfloat16 l0 = __float2bfloat16(v.x - __bfloat162float(h0));
    __nv_bfloat16 l1 = __float2bfloat16(v.y - __bfloat162float(h1));
    __nv_bfloat16 l2 = __float2bfloat16(v.z - __bfloat162float(h2));
    __nv_bfloat16 l3 = __float2bfloat16(v.w - __bfloat162float(h3));
    uint2 H, L;
    H.x = pk2(h0, h1); H.y = pk2(h2, h3);
    L.x = pk2(l0, l1); L.y = pk2(l2, l3);
    hi[i] = H; lo[i] = L;
}

// ---------------- LayerNorm -> bf16 hi/lo planes ----------------
__global__ __launch_bounds__(256) void ln_kernel(
    const float* __restrict__ x, const float* __restrict__ g,
    const float* __restrict__ b)
{
    int row = blockIdx.x;
    const float* xr = x + (size_t)row * DM;
    float s = 0.f, s2 = 0.f;
    for (int i = threadIdx.x; i < DM; i += 256) {
        float v = xr[i];
        s += v; s2 += v * v;
    }
    #pragma unroll
    for (int o = 16; o; o >>= 1) {
        s  += __shfl_xor_sync(0xffffffffu, s,  o);
        s2 += __shfl_xor_sync(0xffffffffu, s2, o);
    }
    __shared__ float red[16];
    __shared__ float mu_s, rs_s;
    int wid = threadIdx.x >> 5, lane = threadIdx.x & 31;
    if (lane == 0) { red[wid] = s; red[8 + wid] = s2; }
    __syncthreads();
    if (threadIdx.x == 0) {
        float S = 0.f, S2 = 0.f;
        #pragma unroll
        for (int i = 0; i < 8; i++) { S += red[i]; S2 += red[8 + i]; }
        float mu = S / (float)DM;
        float var = S2 / (float)DM - mu * mu;
        mu_s = mu;
        rs_s = rsqrtf(var + 1e-5f);
    }
    __syncthreads();
    float mu = mu_s, rs = rs_s;
    for (int i = threadIdx.x; i < DM; i += 256) {
        float v = (xr[i] - mu) * rs * g[i] + b[i];
        __nv_bfloat16 h = __float2bfloat16(v);
        g_ahi[(size_t)row * DM + i] = h;
        g_alo[(size_t)row * DM + i] = __float2bfloat16(v - __bfloat162float(h));
    }
}

// ---------------- depthwise causal conv (DC=7) + SiLU -> bf16 hi/lo ----------------
__global__ __launch_bounds__(256) void conv_silu_kernel(
    const float* __restrict__ cw, const float* __restrict__ cb)
{
    int idx = blockIdx.x * 256 + threadIdx.x;
    int d   = idx % DI;
    int row = idx / DI;
    int t   = row & (LL - 1);
    float s = cb[d];
    #pragma unroll
    for (int k = 0; k < DC; k++) {
        int tt = t - (DC - 1) + k;
        if (tt >= 0)
            s = fmaf(g_xz[(size_t)(row - (DC - 1) + k) * XZW + d], cw[d * DC + k], s);
    }
    float r = s / (1.f + __expf(-s));
    __nv_bfloat16 h = __float2bfloat16(r);
    g_ahi[idx] = h;
    g_alo[idx] = __float2bfloat16(r - __bfloat162float(h));
}

// ---------------- precompute packed scan inputs ----------------
__global__ __launch_bounds__(256) void pre_kernel(const float* __restrict__ Dv)
{
    int idx = blockIdx.x * 256 + threadIdx.x;
    int d   = idx % DI;
    int row = idx / DI;
    float xv = g_xp[(size_t)row * XPW + 2 * DS + d];
    float delta = (xv > 15.f) ? xv : __logf(1.f + __expf(xv));
    float xc = __bfloat162float(g_ahi[idx]) + __bfloat162float(g_alo[idx]);
    float z  = g_xz[(size_t)row * XZW + DI + d];
    float gt = z / (1.f + __expf(-z));
    g_pack[idx] = make_float4(delta, delta * xc, gt, xc * Dv[d] * gt);
}

// ---------------- segmented scan, pass 1: per-segment (h_end, aprod) ----------------
__global__ __launch_bounds__(128) void scan_p1(const float* __restrict__ A_log)
{
    int w    = blockIdx.x * 4 + (threadIdx.x >> 5);   // (bd * NSEG + seg)
    int lane = threadIdx.x & 31;
    int seg  = w & (NSEG - 1);
    int bd   = w >> 3;
    int b    = bd / DI;
    int d    = bd - b * DI;

    float An2 = -__expf(A_log[d * DS + lane]) * 1.4426950408889634f;
    int t0 = seg * SEGLEN;
    const float* pB = g_xp + (size_t)(b * LL + t0) * XPW + lane;
    const float4* pk = g_pack + (size_t)(b * LL + t0) * DI + d;

    float h = 0.f, ap = 1.f;
    #pragma unroll 4
    for (int t = 0; t < SEGLEN; ++t) {
        float2 P = *(const float2*)pk;      // (delta, delta*xc)
        float Bn = pB[0];
        float dA = exp2f(P.x * An2);
        h = fmaf(dA, h, P.y * Bn);
        ap *= dA;
        pk += DI; pB += XPW;
    }
    g_seg[(size_t)w * DS + lane] = make_float2(h, ap);
}

// ---------------- segmented scan, pass 2: combine across NSEG segments ----------------
__global__ __launch_bounds__(256) void scan_p2()
{
    int i = blockIdx.x * 256 + threadIdx.x;   // 0 .. BB*DI*DS-1
    int bd = i >> 5, lane = i & 31;
    float h = 0.f;
    #pragma unroll
    for (int s = 0; s < NSEG; s++) {
        size_t idx = ((size_t)bd * NSEG + s) * DS + lane;
        float2 v = g_seg[idx];
        g_init[idx] = h;
        h = fmaf(v.y, h, v.x);     // h_end_global = local_end + aprod * h_init
    }
}

// ---------------- segmented scan, pass 3: full scan within segment + y out ----------
__global__ __launch_bounds__(128) void scan_p3(const float* __restrict__ A_log)
{
    int w    = blockIdx.x * 4 + (threadIdx.x >> 5);
    int lane = threadIdx.x & 31;
    int seg  = w & (NSEG - 1);
    int bd   = w >> 3;
    int b    = bd / DI;
    int d    = bd - b * DI;

    float An2 = -__expf(A_log[d * DS + lane]) * 1.4426950408889634f;
    int t0 = seg * SEGLEN;
    const float* pB = g_xp + (size_t)(b * LL + t0) * XPW + lane;
    const float4* pk = g_pack + (size_t)(b * LL + t0) * DI + d;
    __nv_bfloat16* pyh = g_ahi + (size_t)(b * LL + t0) * DI + d;
    __nv_bfloat16* pyl = g_alo + (size_t)(b * LL + t0) * DI + d;

    float h = g_init[(size_t)w * DS + lane];
    #pragma unroll 4
    for (int t = 0; t < SEGLEN; ++t) {
        float Bn = pB[0];
        float Cn = pB[DS];
        float4 P = *pk;
        float dA = exp2f(P.x * An2);
        h = fmaf(dA, h, P.y * Bn);
        float p = h * Cn;
        p += __shfl_xor_sync(0xffffffffu, p, 16);
        p += __shfl_xor_sync(0xffffffffu, p, 8);
        p += __shfl_xor_sync(0xffffffffu, p, 4);
        p += __shfl_xor_sync(0xffffffffu, p, 2);
        p += __shfl_xor_sync(0xffffffffu, p, 1);
        if (lane == 0) {
            float yv = fmaf(p, P.z, P.w);
            __nv_bfloat16 yh = __float2bfloat16(yv);
            pyh[0] = yh;
            pyl[0] = __float2bfloat16(yv - __bfloat162float(yh));
        }
        pB += XPW; pk += DI; pyh += DI; pyl += DI;
    }
}

// ---------------- launch ----------------
extern "C" void kernel_launch(void* const* d_in, const int* in_sizes, int n_in,
                              void* d_out, int out_size)
{
    (void)in_sizes; (void)n_in; (void)out_size;
    const float* x      = (const float*)d_in[0];
    const float* Win    = (const float*)d_in[1];
    const float* conv_w = (const float*)d_in[2];
    const float* conv_b = (const float*)d_in[3];
    const float* Wx     = (const float*)d_in[4];
    const float* A_log  = (const float*)d_in[5];
    const float* Dv     = (const float*)d_in[6];
    const float* Wout   = (const float*)d_in[7];
    const float* ln_g   = (const float*)d_in[8];
    const float* ln_b   = (const float*)d_in[9];
    float* out = (float*)d_out;

    void *p_xz, *p_xp, *p_ahi, *p_alo;
    void *p_whi1, *p_wlo1, *p_whi2, *p_wlo2, *p_whi3, *p_wlo3;
    cudaGetSymbolAddress(&p_xz,  g_xz);
    cudaGetSymbolAddress(&p_xp,  g_xp);
    cudaGetSymbolAddress(&p_ahi, g_ahi);
    cudaGetSymbolAddress(&p_alo, g_alo);
    cudaGetSymbolAddress(&p_whi1, g_whi1);
    cudaGetSymbolAddress(&p_wlo1, g_wlo1);
    cudaGetSymbolAddress(&p_whi2, g_whi2);
    cudaGetSymbolAddress(&p_wlo2, g_wlo2);
    cudaGetSymbolAddress(&p_whi3, g_whi3);
    cudaGetSymbolAddress(&p_wlo3, g_wlo3);

    const __nv_bfloat16* ahi = (const __nv_bfloat16*)p_ahi;
    const __nv_bfloat16* alo = (const __nv_bfloat16*)p_alo;

    cudaFuncSetAttribute((const void*)tc_gemm<768, XZW>,
                         cudaFuncAttributeMaxDynamicSharedMemorySize, SMEM_BYTES);
    cudaFuncSetAttribute((const void*)tc_gemm<1536, XPW>,
                         cudaFuncAttributeMaxDynamicSharedMemorySize, SMEM_BYTES);
    cudaFuncSetAttribute((const void*)tc_gemm<1536, DM>,
                         cudaFuncAttributeMaxDynamicSharedMemorySize, SMEM_BYTES);

    // 0. split-convert Win (3072x768)
    cvt_split<<<2304, 256>>>((const float4*)Win, (uint2*)p_whi1, (uint2*)p_wlo1,
                             589824, 589824);

    // 1. split-convert Wx (1600x1536 -> padded 1664)
    cvt_split<<<2496, 256>>>((const float4*)Wx, (uint2*)p_whi2, (uint2*)p_wlo2,
                             638976, 614400);

    // 2. LayerNorm (writes xn hi/lo planes directly)
    ln_kernel<<<BL, 256>>>(x, ln_g, ln_b);

    // 3. xz = xn @ Win^T   (4096 x 3072 x 768)
    tc_gemm<768, XZW><<<dim3(24, 32), 256, SMEM_BYTES>>>(
        ahi, alo, (const __nv_bfloat16*)p_whi1, (const __nv_bfloat16*)p_wlo1,
        nullptr, (float*)p_xz);

    // 4. depthwise conv + silu (writes xcv hi/lo planes directly)
    conv_silu_kernel<<<(BL * DI) / 256, 256>>>(conv_w, conv_b);

    // 5. xp = xcv @ Wx^T   (4096 x 1600 x 1536)
    tc_gemm<1536, XPW><<<dim3(13, 32), 256, SMEM_BYTES>>>(
        ahi, alo, (const __nv_bfloat16*)p_whi2, (const __nv_bfloat16*)p_wlo2,
        nullptr, (float*)p_xp);

    // 6. precompute packed scan inputs
    pre_kernel<<<(BL * DI) / 256, 256>>>(Dv);

    // 7. segmented selective scan (8x parallel; writes y hi/lo planes directly)
    scan_p1<<<(BB * DI * NSEG) / 4, 128>>>(A_log);
    scan_p2<<<(BB * DI * DS) / 256, 256>>>();
    scan_p3<<<(BB * DI * NSEG) / 4, 128>>>(A_log);

    // 8. split-convert Wout (768x1536)
    cvt_split<<<1152, 256>>>((const float4*)Wout, (uint2*)p_whi3, (uint2*)p_wlo3,
                             294912, 294912);

    // 9. out = y @ Wout^T + x   (4096 x 768 x 1536)
    tc_gemm<1536, DM><<<dim3(6, 32), 256, SMEM_BYTES>>>(
        ahi, alo, (const __nv_bfloat16*)p_whi3, (const __nv_bfloat16*)p_wlo3,
        x, out);
}